// round 2
// baseline (speedup 1.0000x reference)
#include <cuda_runtime.h>

#define N_NODES 100000
#define N_EDGES 1600000
#define D_IN    256
#define HF      128     // N_HEADS * D_OUT
#define NEG_SLOPE 0.2f

#define SCAN_BLK 256
#define N_SCAN_BLOCKS ((N_NODES + SCAN_BLK - 1) / SCAN_BLK)   // 391

// ---------------- scratch (device globals: allocation-free) ----------------
__device__ float  g_ft[(size_t)N_NODES * HF];        // 51.2 MB projected features
__device__ float4 g_el[N_NODES];                     // per-node left logits [N][4]
__device__ float4 g_er[N_NODES];                     // per-node right logits [N][4]
__device__ unsigned long long g_wt2[(D_IN / 2) * HF];// W repacked as k-pairs, [k2][c]
__device__ int g_counts[N_NODES];
__device__ int g_offsets[N_NODES];
__device__ int g_cursor[N_NODES];
__device__ int g_bsums[N_SCAN_BLOCKS];
__device__ int g_src_sorted[N_EDGES];

// ---------------- f32x2 helpers (Blackwell packed fp32) ----------------
__device__ __forceinline__ unsigned long long pack2(float lo, float hi) {
    unsigned long long r;
    asm("mov.b64 %0, {%1, %2};" : "=l"(r)
        : "r"(__float_as_uint(lo)), "r"(__float_as_uint(hi)));
    return r;
}
__device__ __forceinline__ void unpack2(unsigned long long v, float& lo, float& hi) {
    unsigned int a, b;
    asm("mov.b64 {%0, %1}, %2;" : "=r"(a), "=r"(b) : "l"(v));
    lo = __uint_as_float(a);
    hi = __uint_as_float(b);
}
__device__ __forceinline__ unsigned long long ffma2(unsigned long long a,
                                                    unsigned long long b,
                                                    unsigned long long c) {
    unsigned long long d;
    asm("fma.rn.f32x2 %0, %1, %2, %3;" : "=l"(d) : "l"(a), "l"(b), "l"(c));
    return d;
}

// ---------------- 0. zero counters ----------------
__global__ void zero_kernel() {
    int i = blockIdx.x * blockDim.x + threadIdx.x;
    if (i < N_NODES) { g_counts[i] = 0; g_cursor[i] = 0; }
}

// ---------------- 1. repack W: wt2[k2*128+c] = (W[c][2k2], W[c][2k2+1]) ----------------
__global__ void wtrans_kernel(const float* __restrict__ w) {
    int idx = blockIdx.x * blockDim.x + threadIdx.x;
    if (idx < (D_IN / 2) * HF) {
        int c  = idx & (HF - 1);
        int k2 = idx >> 7;
        g_wt2[idx] = pack2(w[c * D_IN + 2 * k2], w[c * D_IN + 2 * k2 + 1]);
    }
}

// ---------------- 2. GEMM: ft[n][c] = sum_k x[n][k]*W[c][k], f32x2 packed over k ----------------
#define TILE_ROWS 32
__global__ void __launch_bounds__(512) gemm_kernel(const float* __restrict__ x) {
    __shared__ float xs[TILE_ROWS * D_IN];   // 32 KB, row-major, straight copy
    int tid = threadIdx.x;
    int c   = tid & 127;       // output column (0..127)
    int rg  = tid >> 7;        // row group (0..3), 8 rows each

    int row0 = blockIdx.x * TILE_ROWS;

    // coalesced float4 copy of the x tile (32 rows x 256 cols)
    const float4* xg  = (const float4*)(x + (size_t)row0 * D_IN);
    float4*       xs4 = (float4*)xs;
#pragma unroll
    for (int i = 0; i < 4; i++) xs4[tid + 512 * i] = __ldg(&xg[tid + 512 * i]);
    __syncthreads();

    unsigned long long acc[8];
#pragma unroll
    for (int r = 0; r < 8; r++) acc[r] = 0ULL;

    const unsigned long long* wp = g_wt2 + c;
    const float* xr = xs + (rg * 8) * D_IN;

#pragma unroll 4
    for (int k2 = 0; k2 < D_IN / 2; k2++) {
        unsigned long long w = __ldg(wp + (size_t)k2 * HF);   // coalesced, L1-resident
#pragma unroll
        for (int r = 0; r < 8; r++) {
            // same address across the warp -> broadcast LDS.64 (8B aligned: even index)
            unsigned long long xv =
                *(const unsigned long long*)(xr + r * D_IN + 2 * k2);
            acc[r] = ffma2(xv, w, acc[r]);
        }
    }

#pragma unroll
    for (int r = 0; r < 8; r++) {
        float lo, hi; unpack2(acc[r], lo, hi);
        g_ft[(size_t)(row0 + rg * 8 + r) * HF + c] = lo + hi;  // coalesced store
    }
}

// ---------------- 3. per-node logits el/er (warp per node) ----------------
__global__ void elr_kernel(const float* __restrict__ al, const float* __restrict__ ar) {
    int n    = (blockIdx.x * blockDim.x + threadIdx.x) >> 5;
    int lane = threadIdx.x & 31;
    if (n >= N_NODES) return;
    const float* fr = g_ft + (size_t)n * HF;
    float ol[4], orr[4];
#pragma unroll
    for (int h = 0; h < 4; h++) {
        float v = fr[h * 32 + lane];
        float l = v * __ldg(al + h * 32 + lane);
        float r = v * __ldg(ar + h * 32 + lane);
#pragma unroll
        for (int o = 16; o; o >>= 1) {
            l += __shfl_xor_sync(0xffffffffu, l, o);
            r += __shfl_xor_sync(0xffffffffu, r, o);
        }
        ol[h] = l; orr[h] = r;
    }
    if (lane == 0) {
        g_el[n] = make_float4(ol[0], ol[1], ol[2], ol[3]);
        g_er[n] = make_float4(orr[0], orr[1], orr[2], orr[3]);
    }
}

// ---------------- 4. histogram of dst (dst is int32!) ----------------
__global__ void hist_kernel(const int* __restrict__ dst) {
    int i = blockIdx.x * blockDim.x + threadIdx.x;
    if (i < N_EDGES) atomicAdd(&g_counts[dst[i]], 1);
}

// ---------------- 5. two-level exclusive scan (coalesced) ----------------
__global__ void scanA_kernel() {  // grid N_SCAN_BLOCKS, block 256
    __shared__ int sm[SCAN_BLK];
    int t = threadIdx.x;
    int i = blockIdx.x * SCAN_BLK + t;
    int v = (i < N_NODES) ? g_counts[i] : 0;
    sm[t] = v; __syncthreads();
    for (int off = 1; off < SCAN_BLK; off <<= 1) {
        int u = (t >= off) ? sm[t - off] : 0;
        __syncthreads();
        sm[t] += u;
        __syncthreads();
    }
    if (i < N_NODES) g_offsets[i] = sm[t] - v;          // block-local exclusive
    if (t == SCAN_BLK - 1) g_bsums[blockIdx.x] = sm[t]; // block total
}

__global__ void __launch_bounds__(512) scanB_kernel() {  // 1 block, 512 threads
    __shared__ int sm[512];
    int t = threadIdx.x;
    int v = (t < N_SCAN_BLOCKS) ? g_bsums[t] : 0;
    sm[t] = v; __syncthreads();
    for (int off = 1; off < 512; off <<= 1) {
        int u = (t >= off) ? sm[t - off] : 0;
        __syncthreads();
        sm[t] += u;
        __syncthreads();
    }
    if (t < N_SCAN_BLOCKS) g_bsums[t] = sm[t] - v;      // exclusive block prefix
}

__global__ void scanC_kernel() {
    int i = blockIdx.x * blockDim.x + threadIdx.x;
    if (i < N_NODES) g_offsets[i] += g_bsums[i >> 8];
}

// ---------------- 6. scatter edges into dst-sorted order (int32 indices) ----------------
__global__ void scatter_kernel(const int* __restrict__ src,
                               const int* __restrict__ dst) {
    int i = blockIdx.x * blockDim.x + threadIdx.x;
    if (i < N_EDGES) {
        int d   = dst[i];
        int pos = g_offsets[d] + atomicAdd(&g_cursor[d], 1);
        g_src_sorted[pos] = src[i];
    }
}

// ---------------- 7. aggregate: warp per dst node, unnormalized softmax ----------------
__global__ void __launch_bounds__(256) agg_kernel(float* __restrict__ out) {
    int n    = (blockIdx.x * blockDim.x + threadIdx.x) >> 5;
    int lane = threadIdx.x & 31;
    if (n >= N_NODES) return;

    int base = __ldg(&g_offsets[n]);
    int deg  = __ldg(&g_counts[n]);
    float4 er4 = g_er[n];

    float a0 = 0.f, a1 = 0.f, a2 = 0.f, a3 = 0.f;
    float d0 = 0.f, d1 = 0.f, d2 = 0.f, d3 = 0.f;

    for (int j0 = 0; j0 < deg; j0 += 32) {
        int j = j0 + lane;
        int s = 0;
        float x0 = 0.f, x1 = 0.f, x2 = 0.f, x3 = 0.f;
        if (j < deg) {
            s = __ldg(&g_src_sorted[base + j]);
            float4 e4 = g_el[s];
            float t;
            t = e4.x + er4.x; t = (t > 0.f) ? t : NEG_SLOPE * t; x0 = __expf(t);
            t = e4.y + er4.y; t = (t > 0.f) ? t : NEG_SLOPE * t; x1 = __expf(t);
            t = e4.z + er4.z; t = (t > 0.f) ? t : NEG_SLOPE * t; x2 = __expf(t);
            t = e4.w + er4.w; t = (t > 0.f) ? t : NEG_SLOPE * t; x3 = __expf(t);
            d0 += x0; d1 += x1; d2 += x2; d3 += x3;
        }
        int m = min(32, deg - j0);
        for (int jj = 0; jj < m; jj++) {
            int   sv = __shfl_sync(0xffffffffu, s,  jj);
            float w0 = __shfl_sync(0xffffffffu, x0, jj);
            float w1 = __shfl_sync(0xffffffffu, x1, jj);
            float w2 = __shfl_sync(0xffffffffu, x2, jj);
            float w3 = __shfl_sync(0xffffffffu, x3, jj);
            const float* fr = g_ft + (size_t)sv * HF;
            a0 += w0 * __ldg(fr + lane);
            a1 += w1 * __ldg(fr + 32 + lane);
            a2 += w2 * __ldg(fr + 64 + lane);
            a3 += w3 * __ldg(fr + 96 + lane);
        }
    }

#pragma unroll
    for (int o = 16; o; o >>= 1) {
        d0 += __shfl_xor_sync(0xffffffffu, d0, o);
        d1 += __shfl_xor_sync(0xffffffffu, d1, o);
        d2 += __shfl_xor_sync(0xffffffffu, d2, o);
        d3 += __shfl_xor_sync(0xffffffffu, d3, o);
    }
    float i0 = (deg > 0) ? 1.f / d0 : 0.f;
    float i1 = (deg > 0) ? 1.f / d1 : 0.f;
    float i2 = (deg > 0) ? 1.f / d2 : 0.f;
    float i3 = (deg > 0) ? 1.f / d3 : 0.f;

    float* orow = out + (size_t)n * HF;
    orow[lane]      = a0 * i0;
    orow[32 + lane] = a1 * i1;
    orow[64 + lane] = a2 * i2;
    orow[96 + lane] = a3 * i3;
}

// ---------------- launch ----------------
extern "C" void kernel_launch(void* const* d_in, const int* in_sizes, int n_in,
                              void* d_out, int out_size) {
    const float* x    = (const float*)d_in[0];
    const float* fc_w = (const float*)d_in[1];
    const float* al   = (const float*)d_in[2];
    const float* ar   = (const float*)d_in[3];
    const int*   src  = (const int*)d_in[4];
    const int*   dst  = (const int*)d_in[5];
    float*       out  = (float*)d_out;

    zero_kernel<<<(N_NODES + 255) / 256, 256>>>();
    wtrans_kernel<<<((D_IN / 2) * HF + 255) / 256, 256>>>(fc_w);
    gemm_kernel<<<N_NODES / TILE_ROWS, 512>>>(x);                    // 3125 blocks
    elr_kernel<<<(N_NODES * 32 + 255) / 256, 256>>>(al, ar);
    hist_kernel<<<(N_EDGES + 255) / 256, 256>>>(dst);
    scanA_kernel<<<N_SCAN_BLOCKS, SCAN_BLK>>>();
    scanB_kernel<<<1, 512>>>();
    scanC_kernel<<<(N_NODES + 255) / 256, 256>>>();
    scatter_kernel<<<(N_EDGES + 255) / 256, 256>>>(src, dst);
    agg_kernel<<<(N_NODES * 32) / 256, 256>>>(out);                  // 12500 blocks
}